// round 3
// baseline (speedup 1.0000x reference)
#include <cuda_runtime.h>

#define NPTS   8192
#define TILE   256
#define NSPLIT 32              // JCHUNK == TILE == 256
#define GAMMA_ 100.0f          // 1 / sigma^2, sigma = 0.1
#define LOG2E  1.4426950408889634f

typedef unsigned long long u64;

// ---- f32x2 packed helpers (Blackwell FFMA2 path, PTX-only) ----
__device__ __forceinline__ u64 pack2(float lo, float hi) {
    u64 r;
    asm("mov.b64 %0, {%1, %2};" : "=l"(r) : "r"(__float_as_uint(lo)), "r"(__float_as_uint(hi)));
    return r;
}
__device__ __forceinline__ void unpack2(u64 v, float& lo, float& hi) {
    unsigned a, b;
    asm("mov.b64 {%0, %1}, %2;" : "=r"(a), "=r"(b) : "l"(v));
    lo = __uint_as_float(a); hi = __uint_as_float(b);
}
__device__ __forceinline__ u64 fma2(u64 a, u64 b, u64 c) {
    u64 r; asm("fma.rn.f32x2 %0, %1, %2, %3;" : "=l"(r) : "l"(a), "l"(b), "l"(c)); return r;
}
__device__ __forceinline__ u64 mul2(u64 a, u64 b) {
    u64 r; asm("mul.rn.f32x2 %0, %1, %2;" : "=l"(r) : "l"(a), "l"(b)); return r;
}
__device__ __forceinline__ u64 add2(u64 a, u64 b) {
    u64 r; asm("add.rn.f32x2 %0, %1, %2;" : "=l"(r) : "l"(a), "l"(b)); return r;
}
__device__ __forceinline__ float ex2a(float x) {
    float r; asm("ex2.approx.f32 %0, %1;" : "=f"(r) : "f"(x)); return r;
}

__global__ void zero_kernel(float* __restrict__ out, int n) {
    int i = blockIdx.x * blockDim.x + threadIdx.x;
    if (i < n) out[i] = 0.0f;
}

// Tile: per j-pair group g (j = 2g, 2g+1), 8 x u64 (16B-aligned, 7 used):
//   [0]=xj0 pair  [1]=xj1 pair  [2]=xj2 pair  [3]=s2 pair (-g*log2e*|xj|^2)
//   [4]=pj0 pair  [5]=pj1 pair  [6]=pj2 pair  [7]=pad
__global__ __launch_bounds__(TILE)
void lddmm_kernel(const float* __restrict__ mom,
                  const float* __restrict__ x,
                  float* __restrict__ out)
{
    __shared__ __align__(16) u64 sj[TILE / 2][8];

    const int tid   = threadIdx.x;
    const int i     = blockIdx.x * TILE + tid;
    const int jbase = blockIdx.y * TILE;

    // ---- fill tile (scalar writes into paired layout) ----
    {
        const int j = jbase + tid;
        const float xj0 = x[3*j], xj1 = x[3*j+1], xj2 = x[3*j+2];
        const float pj0 = mom[3*j], pj1 = mom[3*j+1], pj2 = mom[3*j+2];
        const float s2  = -GAMMA_ * LOG2E * (xj0*xj0 + xj1*xj1 + xj2*xj2);
        float* b = (float*)&sj[tid >> 1][0];
        const int h = tid & 1;
        b[0 + h] = xj0;  b[2 + h] = xj1;  b[4 + h]  = xj2;  b[6 + h]  = s2;
        b[8 + h] = pj0;  b[10 + h] = pj1; b[12 + h] = pj2;
    }

    // ---- per-i constants (dup'd into both f32x2 lanes, loop-invariant) ----
    const float xi0 = x[3*i], xi1 = x[3*i+1], xi2 = x[3*i+2];
    const float p0  = mom[3*i], p1 = mom[3*i+1], p2 = mom[3*i+2];
    const float g2l = 2.0f * GAMMA_ * LOG2E;
    const float aiv = -GAMMA_ * LOG2E * (xi0*xi0 + xi1*xi1 + xi2*xi2);

    const u64 gx0 = pack2(g2l * xi0, g2l * xi0);
    const u64 gx1 = pack2(g2l * xi1, g2l * xi1);
    const u64 gx2 = pack2(g2l * xi2, g2l * xi2);
    const u64 ai  = pack2(aiv, aiv);
    const u64 pi0 = pack2(p0, p0);
    const u64 pi1 = pack2(p1, p1);
    const u64 pi2 = pack2(p2, p2);

    u64 dx0 = 0, dx1 = 0, dx2 = 0;          // sum K*pj     (f32x2: even/odd j)
    u64 ws  = 0, q0 = 0, q1 = 0, q2 = 0;    // sum w, sum w*xj

    __syncthreads();

    #pragma unroll 4
    for (int g = 0; g < TILE / 2; g++) {
        const u64* gp = sj[g];               // broadcast LDS, conflict-free
        const u64 xj0p = gp[0], xj1p = gp[1], xj2p = gp[2], s2p = gp[3];
        const u64 pj0p = gp[4], pj1p = gp[5], pj2p = gp[6];

        // arg = log2e * (-gamma) * |xi-xj|^2, fully FMA-form
        u64 arg = add2(s2p, ai);
        arg = fma2(gx0, xj0p, arg);
        arg = fma2(gx1, xj1p, arg);
        arg = fma2(gx2, xj2p, arg);

        float al, ah; unpack2(arg, al, ah);
        const u64 Kv = pack2(ex2a(al), ex2a(ah));   // K = exp(-g r^2), 2 pairs

        u64 pd = mul2(pi0, pj0p);
        pd = fma2(pi1, pj1p, pd);
        pd = fma2(pi2, pj2p, pd);
        const u64 w = mul2(Kv, pd);

        dx0 = fma2(Kv, pj0p, dx0);
        dx1 = fma2(Kv, pj1p, dx1);
        dx2 = fma2(Kv, pj2p, dx2);
        ws  = add2(ws, w);
        q0  = fma2(w, xj0p, q0);
        q1  = fma2(w, xj1p, q1);
        q2  = fma2(w, xj2p, q2);
    }

    // ---- reduce f32x2 halves, finalize, combine across NSPLIT via atomics ----
    float a, b;
    unpack2(dx0, a, b); const float DX0 = a + b;
    unpack2(dx1, a, b); const float DX1 = a + b;
    unpack2(dx2, a, b); const float DX2 = a + b;
    unpack2(ws,  a, b); const float WS  = a + b;
    unpack2(q0,  a, b); const float Q0  = a + b;
    unpack2(q1,  a, b); const float Q1  = a + b;
    unpack2(q2,  a, b); const float Q2  = a + b;

    const float c = 2.0f * GAMMA_;
    atomicAdd(&out[3*i + 0], c * (xi0 * WS - Q0));   // dmom
    atomicAdd(&out[3*i + 1], c * (xi1 * WS - Q1));
    atomicAdd(&out[3*i + 2], c * (xi2 * WS - Q2));
    atomicAdd(&out[3*NPTS + 3*i + 0], DX0);          // dx
    atomicAdd(&out[3*NPTS + 3*i + 1], DX1);
    atomicAdd(&out[3*NPTS + 3*i + 2], DX2);
}

extern "C" void kernel_launch(void* const* d_in, const int* in_sizes, int n_in,
                              void* d_out, int out_size)
{
    const float* mom = (const float*)d_in[0];   // [1, 8192, 3]
    const float* x   = (const float*)d_in[1];   // [1, 8192, 3]
    float*       out = (float*)d_out;           // [2, 8192, 3] = dmom | dx

    zero_kernel<<<(out_size + 255) / 256, 256>>>(out, out_size);

    dim3 grid(NPTS / TILE, NSPLIT);             // (32, 32) = 1024 CTAs
    lddmm_kernel<<<grid, TILE>>>(mom, x, out);
}

// round 4
// speedup vs baseline: 1.4412x; 1.4412x over previous
#include <cuda_runtime.h>

#define NPTS   8192
#define TILE   256
#define NSPLIT 32              // JCHUNK == TILE == 256
#define GAMMA_ 100.0f          // 1 / sigma^2, sigma = 0.1
#define LOG2E  1.4426950408889634f

__global__ void zero_kernel(float* __restrict__ out, int n) {
    int i = blockIdx.x * blockDim.x + threadIdx.x;
    if (i < n) out[i] = 0.0f;
}

// smem per j: A = (xj0, xj1, xj2, s2j)  where s2j = -gamma*log2e*|xj|^2
//             B = (pj0, pj1, pj2, 0)
__global__ __launch_bounds__(TILE)
void lddmm_kernel(const float* __restrict__ mom,
                  const float* __restrict__ x,
                  float* __restrict__ out)
{
    __shared__ float4 sA[TILE];
    __shared__ float4 sB[TILE];

    const int tid   = threadIdx.x;
    const int i     = blockIdx.x * TILE + tid;
    const int jbase = blockIdx.y * TILE;

    // ---- fill tile ----
    {
        const int j = jbase + tid;
        const float xj0 = x[3*j], xj1 = x[3*j+1], xj2 = x[3*j+2];
        const float s2  = -GAMMA_ * LOG2E * (xj0*xj0 + xj1*xj1 + xj2*xj2);
        sA[tid] = make_float4(xj0, xj1, xj2, s2);
        sB[tid] = make_float4(mom[3*j], mom[3*j+1], mom[3*j+2], 0.f);
    }

    // ---- per-i loop invariants ----
    const float xi0 = x[3*i], xi1 = x[3*i+1], xi2 = x[3*i+2];
    const float pi0 = mom[3*i], pi1 = mom[3*i+1], pi2 = mom[3*i+2];
    const float g2l = 2.0f * GAMMA_ * LOG2E;
    const float gx0 = g2l * xi0, gx1 = g2l * xi1, gx2 = g2l * xi2;
    const float aiv = -GAMMA_ * LOG2E * (xi0*xi0 + xi1*xi1 + xi2*xi2);

    float dx0 = 0.f, dx1 = 0.f, dx2 = 0.f;   // sum K*pj
    float ws  = 0.f;                         // sum w            (w = K*<pi,pj>)
    float q0  = 0.f, q1  = 0.f, q2  = 0.f;   // sum w*xj

    __syncthreads();

    #pragma unroll 8
    for (int k = 0; k < TILE; k++) {
        const float4 XJ = sA[k];             // LDS.128 broadcast
        const float4 PJ = sB[k];

        // arg = -gamma*log2e*|xi-xj|^2  (expanded, bias rides as fma addend)
        float arg = XJ.w;                            // s2j
        arg = fmaf(gx2, XJ.z, arg);
        arg = fmaf(gx1, XJ.y, arg);
        arg = fmaf(gx0, XJ.x, arg);
        arg += aiv;                                  // + (-g*l*|xi|^2)

        float Kv;
        asm("ex2.approx.f32 %0, %1;" : "=f"(Kv) : "f"(arg));

        float pd = pi0 * PJ.x;
        pd = fmaf(pi1, PJ.y, pd);
        pd = fmaf(pi2, PJ.z, pd);
        const float w = Kv * pd;

        dx0 = fmaf(Kv, PJ.x, dx0);
        dx1 = fmaf(Kv, PJ.y, dx1);
        dx2 = fmaf(Kv, PJ.z, dx2);
        ws += w;
        q0  = fmaf(w, XJ.x, q0);
        q1  = fmaf(w, XJ.y, q1);
        q2  = fmaf(w, XJ.z, q2);
    }

    // dmom_i = 2*gamma*(xi*ws - q);  out = [dmom (3N) | dx (3N)]
    const float c = 2.0f * GAMMA_;
    atomicAdd(&out[3*i + 0], c * fmaf(xi0, ws, -q0));
    atomicAdd(&out[3*i + 1], c * fmaf(xi1, ws, -q1));
    atomicAdd(&out[3*i + 2], c * fmaf(xi2, ws, -q2));
    atomicAdd(&out[3*NPTS + 3*i + 0], dx0);
    atomicAdd(&out[3*NPTS + 3*i + 1], dx1);
    atomicAdd(&out[3*NPTS + 3*i + 2], dx2);
}

extern "C" void kernel_launch(void* const* d_in, const int* in_sizes, int n_in,
                              void* d_out, int out_size)
{
    const float* mom = (const float*)d_in[0];   // [1, 8192, 3]
    const float* x   = (const float*)d_in[1];   // [1, 8192, 3]
    float*       out = (float*)d_out;           // [2, 8192, 3] = dmom | dx

    zero_kernel<<<(out_size + 255) / 256, 256>>>(out, out_size);

    dim3 grid(NPTS / TILE, NSPLIT);             // (32, 32) = 1024 CTAs
    lddmm_kernel<<<grid, TILE>>>(mom, x, out);
}